// round 15
// baseline (speedup 1.0000x reference)
#include <cuda_runtime.h>
#include <cuda_pipeline.h>

// ---------------------------------------------------------------------------
// Symmetric contraction (MACE-style) for GB300 — R14.
//   out[b, o_p*U + u] += c_p * x0[i0[b], w_p*U + u] * prod_k x1[b, idx_{p,k}*U + u]
//
// R14 vs R13: isolated test — 896 threads / 7 teams with the NON-hoisted
// R10 loop body (natural 71 regs <= cap 72; R12's spill came from the
// pointer-hoist raising demand past the cap, not from 896 itself).
// Setup chain identical to R13 (3 launches).
// ---------------------------------------------------------------------------

#define U       128
#define NSEG    16
#define S_SEG   32
#define SU      (S_SEG * U)      // 4096 floats per x1 row
#define NX0     10
#define NL      4                // batch rows per group
#define NTHREAD 896
#define NTEAM   7                // teams of 128 threads
#define PCAP    256
#define BSORT_CAP 32768
#define BINFO_CAP 8192
#define GRID_MAIN 148
#define NHB     64               // histogram / scatter stripe blocks

struct BInfo { int bin; int start; int count; };

__device__ int   d_binstart[24];
__device__ int   d_histPart[NHB][16];
__device__ int   d_bsort[BSORT_CAP];
__device__ BInfo d_binfo[BINFO_CAP];
__device__ int   d_ngroups;
__device__ uint2 d_meta[PCAP];            // pre-multiplied operand offsets
__device__ int   d_ends[NSEG * 3];
__device__ int   d_tlist[NTEAM * NSEG];   // LPT segment lists
__device__ int   d_tcnt[NTEAM];
__device__ int   d_spw[PCAP];
__device__ float d_spc[PCAP];
__device__ float d_g0c[NX0 * PCAP * U];   // [row][sorted_path][u]

// ---------------- L1: paths (block 0) || i0 partial histograms --------------
__global__ void k_pre(const int* __restrict__ idx1, const int* __restrict__ w1,
                      const int* __restrict__ o1, const float* __restrict__ c1,
                      const int* __restrict__ idx2, const int* __restrict__ w2,
                      const int* __restrict__ o2, const float* __restrict__ c2,
                      const int* __restrict__ idx3, const int* __restrict__ w3,
                      const int* __restrict__ o3, const float* __restrict__ c3,
                      int P1, int P2, int P3,
                      const int* __restrict__ i0, int B) {
    int t = threadIdx.x;
    if (blockIdx.x > 0) {
        // partial histogram for stripe (blockIdx.x-1)
        __shared__ int h[16];
        if (t < 16) h[t] = 0;
        __syncthreads();
        int hb = blockIdx.x - 1;
        for (int b = hb * blockDim.x + t; b < B; b += NHB * blockDim.x)
            atomicAdd(&h[i0[b] & 15], 1);
        __syncthreads();
        if (t < 16) d_histPart[hb][t] = h[t];
        return;
    }

    // ---- block 0: counting sort of paths + LPT team assignment ----
    __shared__ int cnt[NSEG * 3];
    __shared__ int cur[NSEG * 3];
    int Ptot = P1 + P2 + P3;
    if (t < NSEG * 3) cnt[t] = 0;
    __syncthreads();

    for (int p = t; p < Ptot; p += blockDim.x) {
        int key;
        if (p < P1)            key = o1[p] * 3 + 0;
        else if (p < P1 + P2)  key = o2[p - P1] * 3 + 1;
        else                   key = o3[p - P1 - P2] * 3 + 2;
        atomicAdd(&cnt[key], 1);
    }
    __syncthreads();

    if (t == 0) {
        int run = 0;
        for (int k = 0; k < NSEG * 3; ++k) {
            cur[k] = run; run += cnt[k]; d_ends[k] = run;
        }
        // LPT: assign segments (cost desc) to least-loaded team
        float segc[NSEG];
        for (int s = 0; s < NSEG; ++s)
            segc[s] = 5.f * cnt[s*3] + 9.f * cnt[s*3+1] + 13.f * cnt[s*3+2];
        float load[NTEAM]; int tc[NTEAM];
        for (int k = 0; k < NTEAM; ++k) { load[k] = 0.f; tc[k] = 0; }
        bool used[NSEG];
        for (int s = 0; s < NSEG; ++s) used[s] = false;
        for (int it = 0; it < NSEG; ++it) {
            int best = -1;
            for (int s = 0; s < NSEG; ++s)
                if (!used[s] && (best < 0 || segc[s] > segc[best])) best = s;
            used[best] = true;
            int tm = 0;
            for (int k = 1; k < NTEAM; ++k) if (load[k] < load[tm]) tm = k;
            d_tlist[tm * NSEG + tc[tm]] = best;
            tc[tm]++; load[tm] += segc[best];
        }
        for (int k = 0; k < NTEAM; ++k) d_tcnt[k] = tc[k];
    }
    __syncthreads();

    for (int p = t; p < Ptot; p += blockDim.x) {
        int key, w; uint2 meta; float c;
        if (p < P1) {
            key = o1[p] * 3 + 0;
            meta.x = (unsigned)idx1[p] * U; meta.y = 0;
            w = w1[p]; c = c1[p];
        } else if (p < P1 + P2) {
            int q = p - P1;
            key = o2[q] * 3 + 1;
            meta.x = ((unsigned)idx2[q*2] * U) | (((unsigned)idx2[q*2+1] * U) << 16);
            meta.y = 0;
            w = w2[q]; c = c2[q];
        } else {
            int q = p - P1 - P2;
            key = o3[q] * 3 + 2;
            meta.x = ((unsigned)idx3[q*3] * U) | (((unsigned)idx3[q*3+1] * U) << 16);
            meta.y = (unsigned)idx3[q*3+2] * U;
            w = w3[q]; c = c3[q];
        }
        int pos = atomicAdd(&cur[key], 1);
        d_meta[pos] = meta; d_spw[pos] = w; d_spc[pos] = c;
    }
}

// ---------------- L2: binfo (b0) || scatter stripes || g0c table ------------
__global__ void k_setupB(const float* __restrict__ x0, int Ptot, int rowlen,
                         const int* __restrict__ i0, int B) {
    int bid = blockIdx.x;
    int t = threadIdx.x;
    if (bid == 0) {
        // binfo: totals -> binstart -> group descriptors
        __shared__ int pref[17];
        if (t == 0) {
            int run = 0;
            for (int bin = 0; bin < 16; ++bin) {
                int c = 0;
                for (int h = 0; h < NHB; ++h) c += d_histPart[h][bin];
                d_binstart[bin] = run; run += c;
            }
            d_binstart[16] = run;
            run = 0;
            for (int bin = 0; bin < 16; ++bin) {
                pref[bin] = run;
                int c = d_binstart[bin + 1] - d_binstart[bin];
                run += (c + NL - 1) / NL;
            }
            pref[16] = run;
            d_ngroups = run;
        }
        __syncthreads();
        int nb = pref[16];
        for (int i = t; i < nb && i < BINFO_CAP; i += blockDim.x) {
            int bin = 0;
            while (pref[bin + 1] <= i) ++bin;
            int start = d_binstart[bin] + (i - pref[bin]) * NL;
            d_binfo[i].bin = bin;
            d_binfo[i].start = start;
            d_binfo[i].count = min(NL, d_binstart[bin + 1] - start);
        }
    } else if (bid <= NHB) {
        // scatter stripe hb: per-bin base recomputed locally from d_histPart
        __shared__ int base[16];
        int hb = bid - 1;
        if (t < 16) {
            int before = 0, total_prior_bins = 0;
            for (int h = 0; h < hb; ++h) before += d_histPart[h][t];
            for (int bin = 0; bin < 16; ++bin) {
                if (bin < t) {
                    for (int h = 0; h < NHB; ++h)
                        total_prior_bins += d_histPart[h][bin];
                }
            }
            base[t] = total_prior_bins + before;
        }
        __syncthreads();
        for (int b = hb * blockDim.x + t; b < B; b += NHB * blockDim.x) {
            int pos = atomicAdd(&base[i0[b] & 15], 1);
            if (pos < BSORT_CAP) d_bsort[pos] = b;
        }
    } else {
        int i = (bid - 1 - NHB) * blockDim.x + t;
        int tot = NX0 * Ptot * U;
        if (i >= tot) return;
        int u  = i & (U - 1);
        int sp = (i >> 7) % Ptot;
        int r  = i / (Ptot * U);
        d_g0c[r * (PCAP * U) + sp * U + u] =
            x0[(size_t)r * rowlen + d_spw[sp] * U + u] * d_spc[sp];
    }
}

// ---------------- main contraction kernel (persistent) ----------------------
__global__ __launch_bounds__(NTHREAD, 1)
void k_main(const float* __restrict__ x1, float* __restrict__ out,
            int B, int Ptot) {
    extern __shared__ float sm[];
    float*  g0s   = sm;                            // [Ptot][U]
    float*  x1s   = sm + Ptot * U;                 // 2 buffers x [NL][SU] row-major
    uint2*  metas = (uint2*)(x1s + 2 * NL * SU);   // [Ptot]
    int*    endss = (int*)(metas + PCAP);          // [NSEG*3]
    int*    tlst  = endss + NSEG * 3;              // [NTEAM*NSEG]
    int*    tcnts = tlst + NTEAM * NSEG;           // [NTEAM]

    const int tid  = threadIdx.x;
    const int u    = tid & (U - 1);
    const int team = tid >> 7;

    const int ngroups = d_ngroups;
    int gLo = (int)((long long)blockIdx.x * ngroups / GRID_MAIN);
    int gHi = (int)((long long)(blockIdx.x + 1) * ngroups / GRID_MAIN);
    if (gLo >= gHi) return;

    auto prefetch = [&](int g) {
        BInfo gi = d_binfo[g];
        float* dst = x1s + (g & 1) * (NL * SU);
        int b0 = d_bsort[min(gi.start + 0, B - 1)];
        int b1 = d_bsort[min(gi.start + 1, B - 1)];
        int b2 = d_bsort[min(gi.start + 2, B - 1)];
        int b3 = d_bsort[min(gi.start + 3, B - 1)];
        const float* srcs[NL] = {
            x1 + (size_t)b0 * SU, x1 + (size_t)b1 * SU,
            x1 + (size_t)b2 * SU, x1 + (size_t)b3 * SU };
        for (int j = tid; j < NL * SU / 4; j += NTHREAD) {
            int row = j >> 10;               // SU/4 = 1024 chunks per row
            int off = (j & 1023) * 4;
            __pipeline_memcpy_async(dst + row * SU + off, srcs[row] + off, 16);
        }
    };

    prefetch(gLo);
    __pipeline_commit();

    int curbin = d_binfo[gLo].bin;
    {   // stage metadata + first g0 table under shadow of prefetch
        const float4* src = (const float4*)(d_g0c + (size_t)curbin * (PCAP * U));
        float4* dst = (float4*)g0s;
        int n4 = (Ptot * U) >> 2;
        for (int i = tid; i < n4; i += NTHREAD) dst[i] = __ldg(src + i);
        for (int i = tid; i < Ptot; i += NTHREAD) metas[i] = d_meta[i];
        if (tid < NSEG * 3) endss[tid] = d_ends[tid];
        if (tid < NTEAM * NSEG) tlst[tid] = d_tlist[tid];
        if (tid < NTEAM) tcnts[tid] = d_tcnt[tid];
    }
    __syncthreads();

    const int nseg_t = tcnts[team];

    for (int g = gLo; g < gHi; ++g) {
        BInfo gi = d_binfo[g];
        if (gi.bin != curbin) {
            curbin = gi.bin;
            const float4* src = (const float4*)(d_g0c + (size_t)curbin * (PCAP * U));
            float4* dst = (float4*)g0s;
            int n4 = (Ptot * U) >> 2;
            for (int i = tid; i < n4; i += NTHREAD) dst[i] = __ldg(src + i);
        }
        if (g + 1 < gHi) prefetch(g + 1);
        __pipeline_commit();
        __pipeline_wait_prior(1);
        __syncthreads();

        int nb = gi.count;
        int b0 = d_bsort[gi.start];
        int b1 = d_bsort[min(gi.start + 1, B - 1)];
        int b2 = d_bsort[min(gi.start + 2, B - 1)];
        int b3 = d_bsort[min(gi.start + 3, B - 1)];

        const float* xb = x1s + (g & 1) * (NL * SU);
        #pragma unroll 1
        for (int k = 0; k < nseg_t; ++k) {
            int seg = tlst[team * NSEG + k];
            float a0 = 0.f, a1 = 0.f, a2 = 0.f, a3 = 0.f;
            int p  = seg ? endss[seg * 3 - 1] : 0;
            int e1 = endss[seg * 3 + 0];
            int e2 = endss[seg * 3 + 1];
            int e3 = endss[seg * 3 + 2];
            // degree-1
            #pragma unroll 1
            for (; p < e1; ++p) {
                float gv = g0s[p * U + u];
                int oa = (int)(metas[p].x & 0xFFFFu) + u;
                a0 = fmaf(gv, xb[oa         ], a0);
                a1 = fmaf(gv, xb[oa +     SU], a1);
                a2 = fmaf(gv, xb[oa + 2 * SU], a2);
                a3 = fmaf(gv, xb[oa + 3 * SU], a3);
            }
            // degree-2
            #pragma unroll 1
            for (; p < e2; ++p) {
                float gv = g0s[p * U + u];
                unsigned mx = metas[p].x;
                int oa = (int)(mx & 0xFFFFu) + u;
                int ob = (int)(mx >> 16) + u;
                a0 = fmaf(gv, xb[oa         ] * xb[ob         ], a0);
                a1 = fmaf(gv, xb[oa +     SU] * xb[ob +     SU], a1);
                a2 = fmaf(gv, xb[oa + 2 * SU] * xb[ob + 2 * SU], a2);
                a3 = fmaf(gv, xb[oa + 3 * SU] * xb[ob + 3 * SU], a3);
            }
            // degree-3
            #pragma unroll 1
            for (; p < e3; ++p) {
                float gv = g0s[p * U + u];
                uint2 m = metas[p];
                int oa = (int)(m.x & 0xFFFFu) + u;
                int ob = (int)(m.x >> 16) + u;
                int oc = (int)m.y + u;
                a0 = fmaf(gv, xb[oa         ] * xb[ob         ] * xb[oc         ], a0);
                a1 = fmaf(gv, xb[oa +     SU] * xb[ob +     SU] * xb[oc +     SU], a1);
                a2 = fmaf(gv, xb[oa + 2 * SU] * xb[ob + 2 * SU] * xb[oc + 2 * SU], a2);
                a3 = fmaf(gv, xb[oa + 3 * SU] * xb[ob + 3 * SU] * xb[oc + 3 * SU], a3);
            }
            size_t so = (size_t)seg * U + u;
            out[(size_t)b0 * (NSEG * U) + so] = a0;
            if (nb > 1) out[(size_t)b1 * (NSEG * U) + so] = a1;
            if (nb > 2) out[(size_t)b2 * (NSEG * U) + so] = a2;
            if (nb > 3) out[(size_t)b3 * (NSEG * U) + so] = a3;
        }
        __syncthreads();   // all teams done reading xb before buffer reuse
    }
}

// ---------------- launch -----------------------------------------------------
extern "C" void kernel_launch(void* const* d_in, const int* in_sizes, int n_in,
                              void* d_out, int out_size) {
    const float* x0   = (const float*)d_in[0];
    const int*   i0   = (const int*)  d_in[1];
    const float* x1   = (const float*)d_in[2];
    const int*   idx1 = (const int*)  d_in[3];
    const int*   w1   = (const int*)  d_in[4];
    const int*   o1   = (const int*)  d_in[5];
    const float* c1   = (const float*)d_in[6];
    const int*   idx2 = (const int*)  d_in[7];
    const int*   w2   = (const int*)  d_in[8];
    const int*   o2   = (const int*)  d_in[9];
    const float* c2   = (const float*)d_in[10];
    const int*   idx3 = (const int*)  d_in[11];
    const int*   w3   = (const int*)  d_in[12];
    const int*   o3   = (const int*)  d_in[13];
    const float* c3   = (const float*)d_in[14];

    int P1 = in_sizes[4], P2 = in_sizes[8], P3 = in_sizes[12];
    int Ptot = P1 + P2 + P3;
    int B = in_sizes[1];
    int rowlen = in_sizes[0] / NX0;   // C*U

    k_pre<<<1 + NHB, 256>>>(idx1, w1, o1, c1, idx2, w2, o2, c2,
                            idx3, w3, o3, c3, P1, P2, P3, i0, B);

    int tot = NX0 * Ptot * U;
    int gB = 1 + NHB + (tot + 255) / 256;
    k_setupB<<<gB, 256>>>(x0, Ptot, rowlen, i0, B);

    size_t smem = (size_t)Ptot * U * 4            // g0s
                + (size_t)2 * NL * SU * 4         // x1 double buffer
                + (size_t)PCAP * 8                // metas (uint2)
                + NSEG * 3 * 4                    // endss
                + NTEAM * NSEG * 4 + NTEAM * 4;   // team lists
    cudaFuncSetAttribute(k_main, cudaFuncAttributeMaxDynamicSharedMemorySize,
                         (int)smem);
    k_main<<<GRID_MAIN, NTHREAD, smem>>>(x1, (float*)d_out, B, Ptot);
}

// round 16
// speedup vs baseline: 1.0977x; 1.0977x over previous
#include <cuda_runtime.h>
#include <cuda_pipeline.h>
#include <cuda_fp16.h>

// ---------------------------------------------------------------------------
// Symmetric contraction (MACE-style) for GB300 — R16.
//   out[b, o_p*U + u] += c_p * x0[i0[b], w_p*U + u] * prod_k x1[b, idx_{p,k}*U + u]
//
// R16 vs R13 (config optimum 768/6/hoist; occupancy axis exhausted):
//   * g0 table stored fp16 in smem (built as half in setupB — no extra pass):
//     g0 LDS wavefronts halve (8.8% -> 4.4% of crossbar), table 98 -> 49 KB.
//   * single-barrier pipeline: wait_prior(0) -> sync -> prefetch(g+1) ->
//     compute(g). Trailing sync removed (prefetch writes the buffer already
//     released at the previous barrier). Rare extra sync on bin change.
// ---------------------------------------------------------------------------

#define U       128
#define NSEG    16
#define S_SEG   32
#define SU      (S_SEG * U)      // 4096 floats per x1 row
#define NX0     10
#define NL      4                // batch rows per group
#define NTHREAD 768
#define NTEAM   6                // teams of 128 threads
#define PCAP    256
#define BSORT_CAP 32768
#define BINFO_CAP 8192
#define GRID_MAIN 148
#define NHB     64               // histogram / scatter stripe blocks

struct BInfo { int bin; int start; int count; };

__device__ int    d_binstart[24];
__device__ int    d_histPart[NHB][16];
__device__ int    d_bsort[BSORT_CAP];
__device__ BInfo  d_binfo[BINFO_CAP];
__device__ int    d_ngroups;
__device__ uint2  d_meta[PCAP];            // pre-multiplied operand offsets
__device__ int    d_ends[NSEG * 3];
__device__ int    d_tlist[NTEAM * NSEG];   // LPT segment lists
__device__ int    d_tcnt[NTEAM];
__device__ int    d_spw[PCAP];
__device__ float  d_spc[PCAP];
__device__ __half d_g0h[NX0 * PCAP * U];   // fp16 [row][sorted_path][u]

// ---------------- L1: paths (block 0) || i0 partial histograms --------------
__global__ void k_pre(const int* __restrict__ idx1, const int* __restrict__ w1,
                      const int* __restrict__ o1, const float* __restrict__ c1,
                      const int* __restrict__ idx2, const int* __restrict__ w2,
                      const int* __restrict__ o2, const float* __restrict__ c2,
                      const int* __restrict__ idx3, const int* __restrict__ w3,
                      const int* __restrict__ o3, const float* __restrict__ c3,
                      int P1, int P2, int P3,
                      const int* __restrict__ i0, int B) {
    int t = threadIdx.x;
    if (blockIdx.x > 0) {
        // partial histogram for stripe (blockIdx.x-1)
        __shared__ int h[16];
        if (t < 16) h[t] = 0;
        __syncthreads();
        int hb = blockIdx.x - 1;
        for (int b = hb * blockDim.x + t; b < B; b += NHB * blockDim.x)
            atomicAdd(&h[i0[b] & 15], 1);
        __syncthreads();
        if (t < 16) d_histPart[hb][t] = h[t];
        return;
    }

    // ---- block 0: counting sort of paths + LPT team assignment ----
    __shared__ int cnt[NSEG * 3];
    __shared__ int cur[NSEG * 3];
    int Ptot = P1 + P2 + P3;
    if (t < NSEG * 3) cnt[t] = 0;
    __syncthreads();

    for (int p = t; p < Ptot; p += blockDim.x) {
        int key;
        if (p < P1)            key = o1[p] * 3 + 0;
        else if (p < P1 + P2)  key = o2[p - P1] * 3 + 1;
        else                   key = o3[p - P1 - P2] * 3 + 2;
        atomicAdd(&cnt[key], 1);
    }
    __syncthreads();

    if (t == 0) {
        int run = 0;
        for (int k = 0; k < NSEG * 3; ++k) {
            cur[k] = run; run += cnt[k]; d_ends[k] = run;
        }
        // LPT: assign segments (cost desc) to least-loaded team
        float segc[NSEG];
        for (int s = 0; s < NSEG; ++s)
            segc[s] = 5.f * cnt[s*3] + 9.f * cnt[s*3+1] + 13.f * cnt[s*3+2];
        float load[NTEAM]; int tc[NTEAM];
        for (int k = 0; k < NTEAM; ++k) { load[k] = 0.f; tc[k] = 0; }
        bool used[NSEG];
        for (int s = 0; s < NSEG; ++s) used[s] = false;
        for (int it = 0; it < NSEG; ++it) {
            int best = -1;
            for (int s = 0; s < NSEG; ++s)
                if (!used[s] && (best < 0 || segc[s] > segc[best])) best = s;
            used[best] = true;
            int tm = 0;
            for (int k = 1; k < NTEAM; ++k) if (load[k] < load[tm]) tm = k;
            d_tlist[tm * NSEG + tc[tm]] = best;
            tc[tm]++; load[tm] += segc[best];
        }
        for (int k = 0; k < NTEAM; ++k) d_tcnt[k] = tc[k];
    }
    __syncthreads();

    for (int p = t; p < Ptot; p += blockDim.x) {
        int key, w; uint2 meta; float c;
        if (p < P1) {
            key = o1[p] * 3 + 0;
            meta.x = (unsigned)idx1[p] * U; meta.y = 0;
            w = w1[p]; c = c1[p];
        } else if (p < P1 + P2) {
            int q = p - P1;
            key = o2[q] * 3 + 1;
            meta.x = ((unsigned)idx2[q*2] * U) | (((unsigned)idx2[q*2+1] * U) << 16);
            meta.y = 0;
            w = w2[q]; c = c2[q];
        } else {
            int q = p - P1 - P2;
            key = o3[q] * 3 + 2;
            meta.x = ((unsigned)idx3[q*3] * U) | (((unsigned)idx3[q*3+1] * U) << 16);
            meta.y = (unsigned)idx3[q*3+2] * U;
            w = w3[q]; c = c3[q];
        }
        int pos = atomicAdd(&cur[key], 1);
        d_meta[pos] = meta; d_spw[pos] = w; d_spc[pos] = c;
    }
}

// ---------------- L2: binfo (b0) || scatter stripes || g0h table ------------
__global__ void k_setupB(const float* __restrict__ x0, int Ptot, int rowlen,
                         const int* __restrict__ i0, int B) {
    int bid = blockIdx.x;
    int t = threadIdx.x;
    if (bid == 0) {
        // binfo: totals -> binstart -> group descriptors
        __shared__ int pref[17];
        if (t == 0) {
            int run = 0;
            for (int bin = 0; bin < 16; ++bin) {
                int c = 0;
                for (int h = 0; h < NHB; ++h) c += d_histPart[h][bin];
                d_binstart[bin] = run; run += c;
            }
            d_binstart[16] = run;
            run = 0;
            for (int bin = 0; bin < 16; ++bin) {
                pref[bin] = run;
                int c = d_binstart[bin + 1] - d_binstart[bin];
                run += (c + NL - 1) / NL;
            }
            pref[16] = run;
            d_ngroups = run;
        }
        __syncthreads();
        int nb = pref[16];
        for (int i = t; i < nb && i < BINFO_CAP; i += blockDim.x) {
            int bin = 0;
            while (pref[bin + 1] <= i) ++bin;
            int start = d_binstart[bin] + (i - pref[bin]) * NL;
            d_binfo[i].bin = bin;
            d_binfo[i].start = start;
            d_binfo[i].count = min(NL, d_binstart[bin + 1] - start);
        }
    } else if (bid <= NHB) {
        // scatter stripe hb: per-bin base recomputed locally from d_histPart
        __shared__ int base[16];
        int hb = bid - 1;
        if (t < 16) {
            int before = 0, total_prior_bins = 0;
            for (int h = 0; h < hb; ++h) before += d_histPart[h][t];
            for (int bin = 0; bin < 16; ++bin) {
                if (bin < t) {
                    for (int h = 0; h < NHB; ++h)
                        total_prior_bins += d_histPart[h][bin];
                }
            }
            base[t] = total_prior_bins + before;
        }
        __syncthreads();
        for (int b = hb * blockDim.x + t; b < B; b += NHB * blockDim.x) {
            int pos = atomicAdd(&base[i0[b] & 15], 1);
            if (pos < BSORT_CAP) d_bsort[pos] = b;
        }
    } else {
        int i = (bid - 1 - NHB) * blockDim.x + t;
        int tot = NX0 * Ptot * U;
        if (i >= tot) return;
        int u  = i & (U - 1);
        int sp = (i >> 7) % Ptot;
        int r  = i / (Ptot * U);
        d_g0h[r * (PCAP * U) + sp * U + u] =
            __float2half(x0[(size_t)r * rowlen + d_spw[sp] * U + u] * d_spc[sp]);
    }
}

// ---------------- main contraction kernel (persistent) ----------------------
__global__ __launch_bounds__(NTHREAD, 1)
void k_main(const float* __restrict__ x1, float* __restrict__ out,
            int B, int Ptot) {
    extern __shared__ float sm[];
    __half* g0h   = (__half*)sm;                   // [Ptot][U] fp16
    float*  x1s   = sm + (Ptot * U) / 2;           // 2 buffers x [NL][SU] row-major
    uint2*  metas = (uint2*)(x1s + 2 * NL * SU);   // [Ptot]
    int*    endss = (int*)(metas + PCAP);          // [NSEG*3]
    int*    tlst  = endss + NSEG * 3;              // [NTEAM*NSEG]
    int*    tcnts = tlst + NTEAM * NSEG;           // [NTEAM]

    const int tid  = threadIdx.x;
    const int u    = tid & (U - 1);
    const int team = tid >> 7;

    const int ngroups = d_ngroups;
    int gLo = (int)((long long)blockIdx.x * ngroups / GRID_MAIN);
    int gHi = (int)((long long)(blockIdx.x + 1) * ngroups / GRID_MAIN);
    if (gLo >= gHi) return;

    auto prefetch = [&](int g) {
        BInfo gi = d_binfo[g];
        float* dst = x1s + (g & 1) * (NL * SU);
        int b0 = d_bsort[min(gi.start + 0, B - 1)];
        int b1 = d_bsort[min(gi.start + 1, B - 1)];
        int b2 = d_bsort[min(gi.start + 2, B - 1)];
        int b3 = d_bsort[min(gi.start + 3, B - 1)];
        const float* srcs[NL] = {
            x1 + (size_t)b0 * SU, x1 + (size_t)b1 * SU,
            x1 + (size_t)b2 * SU, x1 + (size_t)b3 * SU };
        for (int j = tid; j < NL * SU / 4; j += NTHREAD) {
            int row = j >> 10;               // SU/4 = 1024 chunks per row
            int off = (j & 1023) * 4;
            __pipeline_memcpy_async(dst + row * SU + off, srcs[row] + off, 16);
        }
        __pipeline_commit();
    };

    auto load_g0 = [&](int bin) {
        const uint4* src = (const uint4*)(d_g0h + (size_t)bin * (PCAP * U));
        uint4* dst = (uint4*)g0h;
        int n16 = (Ptot * U * 2) >> 4;       // bytes/16
        for (int i = tid; i < n16; i += NTHREAD) dst[i] = __ldg(src + i);
    };

    prefetch(gLo);

    int curbin = d_binfo[gLo].bin;
    {   // stage metadata + first g0 table under shadow of prefetch
        load_g0(curbin);
        for (int i = tid; i < Ptot; i += NTHREAD) metas[i] = d_meta[i];
        if (tid < NSEG * 3) endss[tid] = d_ends[tid];
        if (tid < NTEAM * NSEG) tlst[tid] = d_tlist[tid];
        if (tid < NTEAM) tcnts[tid] = d_tcnt[tid];
    }

    const int nseg_t = tcnts[team];   // safe: written by this thread's block? no —
    // tcnts written above by tid<NTEAM then read by all -> needs the barrier below
    __syncthreads();
    const int nseg_team = tcnts[team];
    const __half* g0u = g0h + u;             // loop-invariant +u fold
    (void)nseg_t;

    for (int g = gLo; g < gHi; ++g) {
        BInfo gi = d_binfo[g];

        __pipeline_wait_prior(0);
        __syncthreads();   // staged data visible; prev compute done -> other buffer free

        if (gi.bin != curbin) {            // rare: reload g0 (needs its own fence)
            curbin = gi.bin;
            load_g0(curbin);
            __syncthreads();
        }
        if (g + 1 < gHi) prefetch(g + 1);  // writes buffer released at barrier above

        int nb = gi.count;
        int b0 = d_bsort[gi.start];
        int b1 = d_bsort[min(gi.start + 1, B - 1)];
        int b2 = d_bsort[min(gi.start + 2, B - 1)];
        int b3 = d_bsort[min(gi.start + 3, B - 1)];

        const float* xbu = x1s + (g & 1) * (NL * SU) + u;   // +u folded once
        #pragma unroll 1
        for (int k = 0; k < nseg_team; ++k) {
            int seg = tlst[team * NSEG + k];
            float a0 = 0.f, a1 = 0.f, a2 = 0.f, a3 = 0.f;
            int p  = seg ? endss[seg * 3 - 1] : 0;
            int e1 = endss[seg * 3 + 0];
            int e2 = endss[seg * 3 + 1];
            int e3 = endss[seg * 3 + 2];
            // degree-1
            #pragma unroll 1
            for (; p < e1; ++p) {
                float gv = __half2float(g0u[p * U]);
                int oa = (int)(metas[p].x & 0xFFFFu);
                a0 = fmaf(gv, xbu[oa         ], a0);
                a1 = fmaf(gv, xbu[oa +     SU], a1);
                a2 = fmaf(gv, xbu[oa + 2 * SU], a2);
                a3 = fmaf(gv, xbu[oa + 3 * SU], a3);
            }
            // degree-2
            #pragma unroll 1
            for (; p < e2; ++p) {
                float gv = __half2float(g0u[p * U]);
                unsigned mx = metas[p].x;
                int oa = (int)(mx & 0xFFFFu);
                int ob = (int)(mx >> 16);
                a0 = fmaf(gv, xbu[oa         ] * xbu[ob         ], a0);
                a1 = fmaf(gv, xbu[oa +     SU] * xbu[ob +     SU], a1);
                a2 = fmaf(gv, xbu[oa + 2 * SU] * xbu[ob + 2 * SU], a2);
                a3 = fmaf(gv, xbu[oa + 3 * SU] * xbu[ob + 3 * SU], a3);
            }
            // degree-3
            #pragma unroll 1
            for (; p < e3; ++p) {
                float gv = __half2float(g0u[p * U]);
                uint2 m = metas[p];
                int oa = (int)(m.x & 0xFFFFu);
                int ob = (int)(m.x >> 16);
                int oc = (int)m.y;
                a0 = fmaf(gv, xbu[oa         ] * xbu[ob         ] * xbu[oc         ], a0);
                a1 = fmaf(gv, xbu[oa +     SU] * xbu[ob +     SU] * xbu[oc +     SU], a1);
                a2 = fmaf(gv, xbu[oa + 2 * SU] * xbu[ob + 2 * SU] * xbu[oc + 2 * SU], a2);
                a3 = fmaf(gv, xbu[oa + 3 * SU] * xbu[ob + 3 * SU] * xbu[oc + 3 * SU], a3);
            }
            size_t so = (size_t)seg * U + u;
            out[(size_t)b0 * (NSEG * U) + so] = a0;
            if (nb > 1) out[(size_t)b1 * (NSEG * U) + so] = a1;
            if (nb > 2) out[(size_t)b2 * (NSEG * U) + so] = a2;
            if (nb > 3) out[(size_t)b3 * (NSEG * U) + so] = a3;
        }
        // no trailing barrier: next iteration's leading barrier protects reuse
    }
}

// ---------------- launch -----------------------------------------------------
extern "C" void kernel_launch(void* const* d_in, const int* in_sizes, int n_in,
                              void* d_out, int out_size) {
    const float* x0   = (const float*)d_in[0];
    const int*   i0   = (const int*)  d_in[1];
    const float* x1   = (const float*)d_in[2];
    const int*   idx1 = (const int*)  d_in[3];
    const int*   w1   = (const int*)  d_in[4];
    const int*   o1   = (const int*)  d_in[5];
    const float* c1   = (const float*)d_in[6];
    const int*   idx2 = (const int*)  d_in[7];
    const int*   w2   = (const int*)  d_in[8];
    const int*   o2   = (const int*)  d_in[9];
    const float* c2   = (const float*)d_in[10];
    const int*   idx3 = (const int*)  d_in[11];
    const int*   w3   = (const int*)  d_in[12];
    const int*   o3   = (const int*)  d_in[13];
    const float* c3   = (const float*)d_in[14];

    int P1 = in_sizes[4], P2 = in_sizes[8], P3 = in_sizes[12];
    int Ptot = P1 + P2 + P3;
    int B = in_sizes[1];
    int rowlen = in_sizes[0] / NX0;   // C*U

    k_pre<<<1 + NHB, 256>>>(idx1, w1, o1, c1, idx2, w2, o2, c2,
                            idx3, w3, o3, c3, P1, P2, P3, i0, B);

    int tot = NX0 * Ptot * U;
    int gB = 1 + NHB + (tot + 255) / 256;
    k_setupB<<<gB, 256>>>(x0, Ptot, rowlen, i0, B);

    size_t smem = (size_t)Ptot * U * 2            // g0h (fp16)
                + (size_t)2 * NL * SU * 4         // x1 double buffer
                + (size_t)PCAP * 8                // metas (uint2)
                + NSEG * 3 * 4                    // endss
                + NTEAM * NSEG * 4 + NTEAM * 4;   // team lists
    cudaFuncSetAttribute(k_main, cudaFuncAttributeMaxDynamicSharedMemorySize,
                         (int)smem);
    k_main<<<GRID_MAIN, NTHREAD, smem>>>(x1, (float*)d_out, B, Ptot);
}